// round 2
// baseline (speedup 1.0000x reference)
#include <cuda_runtime.h>

#define B_TOTAL  8192
#define T_STEPS  512
#define HID      128
#define BM       64      // batch rows per CTA (32 row-pairs)
#define PITCH    132     // 128 h + 2 x + 2 zero-pad
#define NTHREADS 256
#define ALPHA_C  0.2f
#define BETA_C   0.7f

typedef unsigned long long u64;

__device__ __forceinline__ u64 pack2(float lo, float hi) {
    u64 r; asm("mov.b64 %0, {%1, %2};" : "=l"(r) : "f"(lo), "f"(hi)); return r;
}
__device__ __forceinline__ void unpack2(u64 v, float& lo, float& hi) {
    asm("mov.b64 {%0, %1}, %2;" : "=f"(lo), "=f"(hi) : "l"(v));
}
// Packed dual FMA: c.lo += a.lo*b.lo; c.hi += a.hi*b.hi  (SASS FFMA2)
__device__ __forceinline__ void fma2(u64& c, u64 a, u64 b) {
    asm("fma.rn.f32x2 %0, %1, %2, %0;" : "+l"(c) : "l"(a), "l"(b));
}

__device__ __forceinline__ float tanh_fast(float x) {
    float e = __expf(2.0f * x);
    return 1.0f - __fdividef(2.0f, e + 1.0f);
}

extern __shared__ float smem[];

__global__ __launch_bounds__(NTHREADS, 1)
void rnn_kernel(const float* __restrict__ input,   // (B, T, 2)
                const float* __restrict__ W_rec,   // (130, 128)
                const float* __restrict__ b_rec,   // (128)
                const float* __restrict__ W_out,   // (128, 1)
                const float* __restrict__ b_out,   // (1)
                float* __restrict__ out)           // (B)
{
    // sW: duplicated weights [PITCH][2*HID]: sW[k*256+2n] = sW[k*256+2n+1] = W'[k][n]
    // sA: pair-interleaved state [32 pairs][PITCH][2]: {row 2P, row 2P+1} per k
    float* sW = smem;                       // 132*256 = 33792 floats
    float* sA = smem + PITCH * 2 * HID;     // 32*264  =  8448 floats

    const int tid = threadIdx.x;
    const int cg  = tid & 31;   // lane: 4 n-columns (n0..n0+3)
    const int rg  = tid >> 5;   // warp: 8 m-rows = 4 row-pairs
    const int n0  = cg * 4;
    const int rgP = rg * 4;                 // first pair index
    const int rowBase = rg * 8;
    const int bBase   = blockIdx.x * BM;

    // Build duplicated, reordered W: k<128 -> W_rec[k+2] (h), 128/129 -> x, >=130 -> 0
    for (int idx = tid; idx < PITCH * HID; idx += NTHREADS) {
        int k = idx >> 7;
        int n = idx & 127;
        float v;
        if      (k < 128) v = W_rec[(k + 2) * HID + n];
        else if (k < 130) v = W_rec[(k - 128) * HID + n];
        else              v = 0.0f;
        sW[k * 256 + 2 * n]     = v;
        sW[k * 256 + 2 * n + 1] = v;
    }
    // Zero state tile (h_{-1}=0, pads=0)
    for (int idx = tid; idx < BM * PITCH; idx += NTHREADS) sA[idx] = 0.0f;

    float wout[4];
    u64   bias2[4];
    #pragma unroll
    for (int n = 0; n < 4; n++) {
        float b = b_rec[n0 + n];
        bias2[n] = pack2(b, b);
        wout[n]  = W_out[n0 + n];
    }
    const float bout = b_out[0];

    // Lanes 0..7 each own one batch row
    const int  myLocalRow = rowBase + cg;
    const int  myP   = myLocalRow >> 1;
    const int  myPar = myLocalRow & 1;
    const long long rowOff = (long long)(bBase + myLocalRow) * T_STEPS * 2;

    float  sig2 = 0.0f, prevx0 = 0.0f;
    float2 xcur = make_float2(0.0f, 0.0f);
    if (cg < 8) {
        xcur = *(const float2*)(input + rowOff);       // x_0
        sA[myP * 264 + 256 + myPar] = xcur.x;          // k=128
        sA[myP * 264 + 258 + myPar] = xcur.y;          // k=129
    }
    __syncthreads();

    for (int t = 0; t < T_STEPS; ++t) {
        // Prefetch x_{t+1}
        float2 xnext = make_float2(0.0f, 0.0f);
        if (cg < 8 && t + 1 < T_STEPS)
            xnext = *(const float2*)(input + rowOff + (long long)(t + 1) * 2);

        u64 acc2[4][4];   // [pair j][n-col nn] packed {row 2j, row 2j+1}
        #pragma unroll
        for (int j = 0; j < 4; j++) {
            acc2[j][0] = bias2[0]; acc2[j][1] = bias2[1];
            acc2[j][2] = bias2[2]; acc2[j][3] = bias2[3];
        }

        // GEMM: 33 kq iters × (16 LDS + 64 FFMA2)
        #pragma unroll 3
        for (int kq = 0; kq < PITCH / 4; ++kq) {
            u64 a2[4][4];   // [pair][kk], each packed {A[2P][k], A[2P+1][k]}
            #pragma unroll
            for (int j = 0; j < 4; j++) {
                const float* base = sA + (rgP + j) * 264 + 8 * kq;
                ulonglong2 lo = *(const ulonglong2*)(base);       // k, k+1
                ulonglong2 hi = *(const ulonglong2*)(base + 4);   // k+2, k+3
                a2[j][0] = lo.x; a2[j][1] = lo.y;
                a2[j][2] = hi.x; a2[j][3] = hi.y;
            }
            #pragma unroll
            for (int kk = 0; kk < 4; kk++) {
                const float* wb = sW + (4 * kq + kk) * 256 + 8 * cg;
                ulonglong2 w0 = *(const ulonglong2*)(wb);         // {w[n0],w[n0]},{w[n0+1],w[n0+1]}
                ulonglong2 w1 = *(const ulonglong2*)(wb + 4);     // {w[n0+2]...},{w[n0+3]...}
                u64 wd[4] = { w0.x, w0.y, w1.x, w1.y };
                #pragma unroll
                for (int j = 0; j < 4; j++) {
                    fma2(acc2[j][0], a2[j][kk], wd[0]);
                    fma2(acc2[j][1], a2[j][kk], wd[1]);
                    fma2(acc2[j][2], a2[j][kk], wd[2]);
                    fma2(acc2[j][3], a2[j][kk], wd[3]);
                }
            }
        }

        // tanh + omega partials (unpack pairs -> per-row)
        float h[8][4];
        float part[8];
        #pragma unroll
        for (int j = 0; j < 4; j++) {
            #pragma unroll
            for (int nn = 0; nn < 4; nn++) {
                float lo, hi;
                unpack2(acc2[j][nn], lo, hi);
                h[2 * j][nn]     = tanh_fast(lo);
                h[2 * j + 1][nn] = tanh_fast(hi);
            }
        }
        #pragma unroll
        for (int m = 0; m < 8; m++) {
            part[m] = h[m][0] * wout[0] + h[m][1] * wout[1]
                    + h[m][2] * wout[2] + h[m][3] * wout[3];
            part[m] += __shfl_xor_sync(0xffffffffu, part[m], 16);
            part[m] += __shfl_xor_sync(0xffffffffu, part[m], 8);
            part[m] += __shfl_xor_sync(0xffffffffu, part[m], 4);
            part[m] += __shfl_xor_sync(0xffffffffu, part[m], 2);
            part[m] += __shfl_xor_sync(0xffffffffu, part[m], 1);
        }

        __syncthreads();   // all reads of sA done before overwrite

        // Write h_t back, pair-interleaved: float2 {row 2j, row 2j+1} at column n
        #pragma unroll
        for (int j = 0; j < 4; j++) {
            #pragma unroll
            for (int nn = 0; nn < 4; nn++) {
                float2 hv = make_float2(h[2 * j][nn], h[2 * j + 1][nn]);
                *(float2*)&sA[(rgP + j) * 264 + (n0 + nn) * 2] = hv;
            }
        }

        if (cg < 8) {
            float om = 0.0f;
            #pragma unroll
            for (int m = 0; m < 8; m++) if (cg == m) om = part[m];
            sig2 = sig2 * BETA_C + prevx0 * prevx0 * ALPHA_C + (om + bout);
            prevx0 = xcur.x;
            sA[myP * 264 + 256 + myPar] = xnext.x;
            sA[myP * 264 + 258 + myPar] = xnext.y;
            xcur = xnext;
        }
        __syncthreads();   // writes visible before next step's reads
    }

    if (cg < 8) out[bBase + myLocalRow] = sig2;
}

extern "C" void kernel_launch(void* const* d_in, const int* in_sizes, int n_in,
                              void* d_out, int out_size) {
    const float* input = (const float*)d_in[0];
    const float* W_rec = (const float*)d_in[1];
    const float* b_rec = (const float*)d_in[2];
    const float* W_out = (const float*)d_in[3];
    const float* b_out = (const float*)d_in[4];
    float* out = (float*)d_out;

    const size_t smem_bytes = (size_t)(PITCH * 2 * HID + BM * PITCH) * sizeof(float); // 168960
    cudaFuncSetAttribute(rnn_kernel, cudaFuncAttributeMaxDynamicSharedMemorySize,
                         (int)smem_bytes);

    rnn_kernel<<<B_TOTAL / BM, NTHREADS, smem_bytes>>>(input, W_rec, b_rec,
                                                       W_out, b_out, out);
    (void)in_sizes; (void)n_in; (void)out_size;
}

// round 3
// speedup vs baseline: 1.8884x; 1.8884x over previous
#include <cuda_runtime.h>

#define B_TOTAL  8192
#define T_STEPS  512
#define HID      128
#define BM       64      // batch rows per CTA (32 row-pairs)
#define PITCH    132     // 128 h + 2 x + 2 zero-pad
#define NTHREADS 256
#define ALPHA_C  0.2f
#define BETA_C   0.7f

typedef unsigned long long u64;

__device__ __forceinline__ u64 pack2(float lo, float hi) {
    u64 r; asm("mov.b64 %0, {%1, %2};" : "=l"(r) : "f"(lo), "f"(hi)); return r;
}
__device__ __forceinline__ void unpack2(u64 v, float& lo, float& hi) {
    asm("mov.b64 {%0, %1}, %2;" : "=f"(lo), "=f"(hi) : "l"(v));
}
// Packed dual FMA: c.lo += a.lo*b.lo; c.hi += a.hi*b.hi  (SASS FFMA2)
__device__ __forceinline__ void fma2(u64& c, u64 a, u64 b) {
    asm("fma.rn.f32x2 %0, %1, %2, %0;" : "+l"(c) : "l"(a), "l"(b));
}

__device__ __forceinline__ float tanh_fast(float x) {
    float e = __expf(2.0f * x);
    return 1.0f - __fdividef(2.0f, e + 1.0f);
}

extern __shared__ float smem[];

__global__ __launch_bounds__(NTHREADS, 1)
void rnn_kernel(const float* __restrict__ input,   // (B, T, 2)
                const float* __restrict__ W_rec,   // (130, 128)
                const float* __restrict__ b_rec,   // (128)
                const float* __restrict__ W_out,   // (128, 1)
                const float* __restrict__ b_out,   // (1)
                float* __restrict__ out)           // (B)
{
    // sW: dense weights [PITCH][HID] (R1 layout): sW[k*128+n]
    // sA: pair-interleaved state [32 pairs][PITCH][2]: {row 2P, row 2P+1} per k
    float* sW = smem;                   // 132*128 = 16896 floats
    float* sA = smem + PITCH * HID;     // 32*264  =  8448 floats

    const int tid = threadIdx.x;
    const int cg  = tid & 31;   // lane: 4 n-columns (n0..n0+3)
    const int rg  = tid >> 5;   // warp: 8 m-rows = 4 row-pairs
    const int n0  = cg * 4;
    const int rgP = rg * 4;                 // first pair index
    const int rowBase = rg * 8;
    const int bBase   = blockIdx.x * BM;

    // Build reordered W: k<128 -> W_rec[k+2] (h), 128/129 -> x, >=130 -> 0
    for (int idx = tid; idx < PITCH * HID; idx += NTHREADS) {
        int k = idx >> 7;
        int n = idx & 127;
        float v;
        if      (k < 128) v = W_rec[(k + 2) * HID + n];
        else if (k < 130) v = W_rec[(k - 128) * HID + n];
        else              v = 0.0f;
        sW[idx] = v;
    }
    // Zero state tile (h_{-1}=0, pads=0)
    for (int idx = tid; idx < BM * PITCH; idx += NTHREADS) sA[idx] = 0.0f;

    float wout[4];
    u64   bias2[4];
    #pragma unroll
    for (int n = 0; n < 4; n++) {
        float b = b_rec[n0 + n];
        bias2[n] = pack2(b, b);
        wout[n]  = W_out[n0 + n];
    }
    const float bout = b_out[0];

    // Lanes 0..7 each own one batch row
    const int  myLocalRow = rowBase + cg;
    const int  myP   = myLocalRow >> 1;
    const int  myPar = myLocalRow & 1;
    const long long rowOff = (long long)(bBase + myLocalRow) * T_STEPS * 2;

    float  sig2 = 0.0f, prevx0 = 0.0f;
    float2 xcur = make_float2(0.0f, 0.0f);
    if (cg < 8) {
        xcur = *(const float2*)(input + rowOff);       // x_0
        sA[myP * 264 + 256 + myPar] = xcur.x;          // k=128
        sA[myP * 264 + 258 + myPar] = xcur.y;          // k=129
    }
    __syncthreads();

    for (int t = 0; t < T_STEPS; ++t) {
        // Prefetch x_{t+1}
        float2 xnext = make_float2(0.0f, 0.0f);
        if (cg < 8 && t + 1 < T_STEPS)
            xnext = *(const float2*)(input + rowOff + (long long)(t + 1) * 2);

        u64 acc2[4][4];   // [pair j][n-col nn] packed {row 2j, row 2j+1}
        #pragma unroll
        for (int j = 0; j < 4; j++) {
            acc2[j][0] = bias2[0]; acc2[j][1] = bias2[1];
            acc2[j][2] = bias2[2]; acc2[j][3] = bias2[3];
        }

        // GEMM: 33 kq iters × (8 broadcast a-LDS + 4 dense w-LDS + 16 packs + 64 FFMA2)
        #pragma unroll 3
        for (int kq = 0; kq < PITCH / 4; ++kq) {
            u64 a2[4][4];   // [pair][kk], each packed {A[2P][k], A[2P+1][k]}
            #pragma unroll
            for (int j = 0; j < 4; j++) {
                const float* base = sA + (rgP + j) * 264 + 8 * kq;
                ulonglong2 lo = *(const ulonglong2*)(base);       // k, k+1
                ulonglong2 hi = *(const ulonglong2*)(base + 4);   // k+2, k+3
                a2[j][0] = lo.x; a2[j][1] = lo.y;
                a2[j][2] = hi.x; a2[j][3] = hi.y;
            }
            #pragma unroll
            for (int kk = 0; kk < 4; kk++) {
                // Dense float4 load of W row, duplicate each scalar into a reg pair
                float4 w = *(const float4*)(sW + (4 * kq + kk) * HID + n0);
                u64 wd[4];
                wd[0] = pack2(w.x, w.x);
                wd[1] = pack2(w.y, w.y);
                wd[2] = pack2(w.z, w.z);
                wd[3] = pack2(w.w, w.w);
                #pragma unroll
                for (int j = 0; j < 4; j++) {
                    fma2(acc2[j][0], a2[j][kk], wd[0]);
                    fma2(acc2[j][1], a2[j][kk], wd[1]);
                    fma2(acc2[j][2], a2[j][kk], wd[2]);
                    fma2(acc2[j][3], a2[j][kk], wd[3]);
                }
            }
        }

        // tanh + omega partials (unpack pairs -> per-row)
        float h[8][4];
        float part[8];
        #pragma unroll
        for (int j = 0; j < 4; j++) {
            #pragma unroll
            for (int nn = 0; nn < 4; nn++) {
                float lo, hi;
                unpack2(acc2[j][nn], lo, hi);
                h[2 * j][nn]     = tanh_fast(lo);
                h[2 * j + 1][nn] = tanh_fast(hi);
            }
        }
        #pragma unroll
        for (int m = 0; m < 8; m++) {
            part[m] = h[m][0] * wout[0] + h[m][1] * wout[1]
                    + h[m][2] * wout[2] + h[m][3] * wout[3];
            part[m] += __shfl_xor_sync(0xffffffffu, part[m], 16);
            part[m] += __shfl_xor_sync(0xffffffffu, part[m], 8);
            part[m] += __shfl_xor_sync(0xffffffffu, part[m], 4);
            part[m] += __shfl_xor_sync(0xffffffffu, part[m], 2);
            part[m] += __shfl_xor_sync(0xffffffffu, part[m], 1);
        }

        __syncthreads();   // all reads of sA done before overwrite

        // Write h_t back, pair-interleaved: float2 {row 2j, row 2j+1} at column n
        #pragma unroll
        for (int j = 0; j < 4; j++) {
            #pragma unroll
            for (int nn = 0; nn < 4; nn++) {
                float2 hv = make_float2(h[2 * j][nn], h[2 * j + 1][nn]);
                *(float2*)&sA[(rgP + j) * 264 + (n0 + nn) * 2] = hv;
            }
        }

        if (cg < 8) {
            float om = 0.0f;
            #pragma unroll
            for (int m = 0; m < 8; m++) if (cg == m) om = part[m];
            sig2 = sig2 * BETA_C + prevx0 * prevx0 * ALPHA_C + (om + bout);
            prevx0 = xcur.x;
            sA[myP * 264 + 256 + myPar] = xnext.x;
            sA[myP * 264 + 258 + myPar] = xnext.y;
            xcur = xnext;
        }
        __syncthreads();   // writes visible before next step's reads
    }

    if (cg < 8) out[bBase + myLocalRow] = sig2;
}

extern "C" void kernel_launch(void* const* d_in, const int* in_sizes, int n_in,
                              void* d_out, int out_size) {
    const float* input = (const float*)d_in[0];
    const float* W_rec = (const float*)d_in[1];
    const float* b_rec = (const float*)d_in[2];
    const float* W_out = (const float*)d_in[3];
    const float* b_out = (const float*)d_in[4];
    float* out = (float*)d_out;

    const size_t smem_bytes = (size_t)(PITCH * HID + BM * PITCH) * sizeof(float); // 101376
    cudaFuncSetAttribute(rnn_kernel, cudaFuncAttributeMaxDynamicSharedMemorySize,
                         (int)smem_bytes);

    rnn_kernel<<<B_TOTAL / BM, NTHREADS, smem_bytes>>>(input, W_rec, b_rec,
                                                       W_out, b_out, out);
    (void)in_sizes; (void)n_in; (void)out_size;
}

// round 5
// speedup vs baseline: 2.0256x; 1.0727x over previous
#include <cuda_runtime.h>

#define B_TOTAL  8192
#define T_STEPS  512
#define HID      128
#define BM       64      // batch rows per CTA (32 row-pairs)
#define NKQ      33      // k-quads: 128 h + 2 x + 2 pad = 132 k's
#define PITCHF   264     // floats per pair-row: 256 h (pair-interleaved) + 4 x/pad
#define NTHREADS 256
#define ALPHA_C  0.2f
#define BETA_C   0.7f

typedef unsigned long long u64;

__device__ __forceinline__ u64 pack2(float lo, float hi) {
    u64 r; asm("mov.b64 %0, {%1, %2};" : "=l"(r) : "f"(lo), "f"(hi)); return r;
}
__device__ __forceinline__ void unpack2(u64 v, float& lo, float& hi) {
    asm("mov.b64 {%0, %1}, %2;" : "=f"(lo), "=f"(hi) : "l"(v));
}
// c += a*b (packed f32x2 -> SASS FFMA2)
__device__ __forceinline__ void fma2(u64& c, u64 a, u64 b) {
    asm("fma.rn.f32x2 %0, %1, %2, %0;" : "+l"(c) : "l"(a), "l"(b));
}
// c = c*b + h (packed)
__device__ __forceinline__ void fma2s(u64& c, u64 b, u64 h) {
    asm("fma.rn.f32x2 %0, %0, %1, %2;" : "+l"(c) : "l"(b), "l"(h));
}

__device__ __forceinline__ float tanh_fast(float x) {
    float e = __expf(2.0f * x);
    return 1.0f - __fdividef(2.0f, e + 1.0f);
}

extern __shared__ float smem[];

__global__ __launch_bounds__(NTHREADS, 1)
void rnn_kernel(const float* __restrict__ input,   // (B, T, 2)
                const float* __restrict__ W_rec,   // (130, 128)
                const float* __restrict__ b_rec,   // (128)
                const float* __restrict__ W_out,   // (128, 1)
                const float* __restrict__ b_out,   // (1)
                float* __restrict__ out)           // (B)
{
    float* sW  = smem;                        // [132][128] dense, k-major
    float* sA0 = smem + 132 * HID;            // 32 pair-rows x 264 floats
    float* sA1 = sA0 + 32 * PITCHF;

    const int tid = threadIdx.x;
    const int cg  = tid & 31;   // lane: 4 n-columns
    const int rg  = tid >> 5;   // warp: 4 row-pairs (8 rows)
    const int n0  = cg * 4;
    const int rgP = rg * 4;
    const int rowBase = rg * 8;
    const int bBase   = blockIdx.x * BM;

    // Reordered W: k<128 -> W_rec[k+2] (hidden), 128/129 -> x, >=130 -> 0
    for (int idx = tid; idx < 132 * HID; idx += NTHREADS) {
        int k = idx >> 7;
        int n = idx & 127;
        float v;
        if      (k < 128) v = W_rec[(k + 2) * HID + n];
        else if (k < 130) v = W_rec[(k - 128) * HID + n];
        else              v = 0.0f;
        sW[idx] = v;
    }
    // Zero both state buffers (h_{-1}=0, pads=0)
    for (int idx = tid; idx < 2 * 32 * PITCHF; idx += NTHREADS) sA0[idx] = 0.0f;

    float wout[4];
    u64   bias2[4];
    #pragma unroll
    for (int n = 0; n < 4; n++) {
        float b = b_rec[n0 + n];
        bias2[n] = pack2(b, b);
        wout[n]  = W_out[n0 + n];
    }
    const float bout = b_out[0];
    const u64 beta2 = pack2(BETA_C, BETA_C);

    const int  myLocalRow = rowBase + cg;      // lanes 0..7 own a batch row
    const int  myP   = myLocalRow >> 1;
    const int  myPar = myLocalRow & 1;
    const long long rowOff = (long long)(bBase + myLocalRow) * T_STEPS * 2;

    float  racc = 0.0f, prevx0 = 0.0f;
    float2 xcur = make_float2(0.0f, 0.0f);
    if (cg < 8) {
        xcur = *(const float2*)(input + rowOff);       // x_0 -> buffer 0
        sA0[myP * PITCHF + 256 + myPar] = xcur.x;
        sA0[myP * PITCHF + 258 + myPar] = xcur.y;
    }
    __syncthreads();

    u64 hacc2[4][4];   // beta-weighted sum of h, packed {row 2j, row 2j+1}
    #pragma unroll
    for (int j = 0; j < 4; j++)
        #pragma unroll
        for (int nn = 0; nn < 4; nn++) hacc2[j][nn] = 0ULL;

    float* cur = sA0;
    float* nxt = sA1;

    for (int t = 0; t < T_STEPS; ++t) {
        // Prefetch x_{t+1}
        float2 xnext = make_float2(0.0f, 0.0f);
        if (cg < 8 && t + 1 < T_STEPS)
            xnext = *(const float2*)(input + rowOff + (long long)(t + 1) * 2);

        u64 acc2[4][4];
        #pragma unroll
        for (int j = 0; j < 4; j++) {
            acc2[j][0] = bias2[0]; acc2[j][1] = bias2[1];
            acc2[j][2] = bias2[2]; acc2[j][3] = bias2[3];
        }

        // GEMM: 33 kq x (8 broadcast a-LDS.128 + 4 w-LDS.128 + 16 packs + 64 FFMA2)
        #pragma unroll 3
        for (int kq = 0; kq < NKQ; ++kq) {
            u64 a2[4][4];
            #pragma unroll
            for (int j = 0; j < 4; j++) {
                const float* base = cur + (rgP + j) * PITCHF + 8 * kq;
                ulonglong2 lo = *(const ulonglong2*)(base);
                ulonglong2 hi = *(const ulonglong2*)(base + 4);
                a2[j][0] = lo.x; a2[j][1] = lo.y;
                a2[j][2] = hi.x; a2[j][3] = hi.y;
            }
            #pragma unroll
            for (int kk = 0; kk < 4; kk++) {
                float4 w = *(const float4*)(sW + (4 * kq + kk) * HID + n0);
                u64 wd[4];
                wd[0] = pack2(w.x, w.x);
                wd[1] = pack2(w.y, w.y);
                wd[2] = pack2(w.z, w.z);
                wd[3] = pack2(w.w, w.w);
                #pragma unroll
                for (int j = 0; j < 4; j++) {
                    fma2(acc2[j][0], a2[j][kk], wd[0]);
                    fma2(acc2[j][1], a2[j][kk], wd[1]);
                    fma2(acc2[j][2], a2[j][kk], wd[2]);
                    fma2(acc2[j][3], a2[j][kk], wd[3]);
                }
            }
        }

        // tanh -> packed h; store (identity layout); beta-accumulate
        #pragma unroll
        for (int j = 0; j < 4; j++) {
            u64 h2[4];
            #pragma unroll
            for (int nn = 0; nn < 4; nn++) {
                float lo, hi;
                unpack2(acc2[j][nn], lo, hi);
                h2[nn] = pack2(tanh_fast(lo), tanh_fast(hi));
            }
            float* dst = nxt + (rgP + j) * PITCHF + 8 * cg;
            ulonglong2 s0; s0.x = h2[0]; s0.y = h2[1];
            ulonglong2 s1; s1.x = h2[2]; s1.y = h2[3];
            *(ulonglong2*)(dst)     = s0;
            *(ulonglong2*)(dst + 4) = s1;
            fma2s(hacc2[j][0], beta2, h2[0]);
            fma2s(hacc2[j][1], beta2, h2[1]);
            fma2s(hacc2[j][2], beta2, h2[2]);
            fma2s(hacc2[j][3], beta2, h2[3]);
        }

        // resid-term recursion (prevx0 is 0 on lanes >= 8 -> harmless)
        racc = racc * BETA_C + prevx0 * prevx0;
        prevx0 = xcur.x;
        if (cg < 8) {
            nxt[myP * PITCHF + 256 + myPar] = xnext.x;
            nxt[myP * PITCHF + 258 + myPar] = xnext.y;
            xcur = xnext;
        }
        __syncthreads();
        float* tmp = cur; cur = nxt; nxt = tmp;
    }

    // One-time reduction: omega-part = hacc . W_out, butterfly over 32 lanes
    float ol[4], oh[4];
    #pragma unroll
    for (int j = 0; j < 4; j++) {
        u64 p2 = 0ULL;
        u64 w2;
        w2 = pack2(wout[0], wout[0]); fma2(p2, hacc2[j][0], w2);
        w2 = pack2(wout[1], wout[1]); fma2(p2, hacc2[j][1], w2);
        w2 = pack2(wout[2], wout[2]); fma2(p2, hacc2[j][2], w2);
        w2 = pack2(wout[3], wout[3]); fma2(p2, hacc2[j][3], w2);
        float lo, hi; unpack2(p2, lo, hi);
        #pragma unroll
        for (int s = 16; s >= 1; s >>= 1) {
            lo += __shfl_xor_sync(0xffffffffu, lo, s);
            hi += __shfl_xor_sync(0xffffffffu, hi, s);
        }
        ol[j] = lo; oh[j] = hi;
    }

    if (cg < 8) {
        const int jj = cg >> 1;
        float om = (jj == 0) ? (myPar ? oh[0] : ol[0])
                 : (jj == 1) ? (myPar ? oh[1] : ol[1])
                 : (jj == 2) ? (myPar ? oh[2] : ol[2])
                 :             (myPar ? oh[3] : ol[3]);
        const float geo = (1.0f - __powf(BETA_C, (float)T_STEPS)) / (1.0f - BETA_C);
        out[bBase + myLocalRow] = racc * ALPHA_C + om + bout * geo;
    }
}

extern "C" void kernel_launch(void* const* d_in, const int* in_sizes, int n_in,
                              void* d_out, int out_size) {
    const float* input = (const float*)d_in[0];
    const float* W_rec = (const float*)d_in[1];
    const float* b_rec = (const float*)d_in[2];
    const float* W_out = (const float*)d_in[3];
    const float* b_out = (const float*)d_in[4];
    float* out = (float*)d_out;

    const size_t smem_bytes = (size_t)(132 * HID + 2 * 32 * PITCHF) * sizeof(float); // 135168
    cudaFuncSetAttribute(rnn_kernel, cudaFuncAttributeMaxDynamicSharedMemorySize,
                         (int)smem_bytes);

    rnn_kernel<<<B_TOTAL / BM, NTHREADS, smem_bytes>>>(input, W_rec, b_rec,
                                                       W_out, b_out, out);
    (void)in_sizes; (void)n_in; (void)out_size;
}